// round 3
// baseline (speedup 1.0000x reference)
#include <cuda_runtime.h>
#include <math.h>

// Problem constants
#define BB   64
#define TMEL 2000
#define EE   512
#define MMI  80
#define PP   256
#define HH   1024
#define TD   1000
#define RR   (TD*BB)   // 64000 rows

// ---------------- static device scratch (allocation-free rule) ----------------
__device__ float g_di [(size_t)RR*MMI];     // teacher-forced prenet input
__device__ float g_mem[(size_t)RR*EE];      // pooled memory  [t][b][512]
__device__ float g_xa [(size_t)RR*PP];
__device__ float g_xb [(size_t)RR*PP];
__device__ float g_gi [(size_t)RR*3*HH];    // precomputed input gates (reused per pass)
__device__ float g_h1 [(size_t)RR*HH];
__device__ float g_h2 [(size_t)RR*HH];
__device__ float g_h3 [(size_t)RR*HH];
__device__ float g_d2 [(size_t)RR*HH];      // d2, later r3
__device__ float g_r2 [(size_t)RR*HH];

// software grid barrier state (zero-initialized at module load; invariant:
// g_barcnt returns to 0 after every barrier, g_bargen monotonically increments)
__device__ unsigned g_barcnt;
__device__ unsigned g_bargen;

// ---------------- prep kernels ----------------
__global__ void pool_kernel(const float* __restrict__ memorys)
{
    // g_mem[t][b][e] = 0.5*(memorys[b][2t][e] + memorys[b][2t+1][e])
    size_t total = (size_t)RR * EE;
    for (size_t i = (size_t)blockIdx.x*blockDim.x + threadIdx.x; i < total;
         i += (size_t)gridDim.x*blockDim.x) {
        int e = (int)(i % EE);
        int tb = (int)(i / EE);
        int b = tb & (BB-1);
        int t = tb >> 6;
        const float* src = memorys + ((size_t)b*TMEL + 2*t)*EE + e;
        g_mem[i] = 0.5f*(src[0] + src[EE]);
    }
}

__global__ void di_kernel(const float* __restrict__ dec)
{
    // g_di[t][b][m] = (t==0) ? 0 : dec[b][2t-1][m]
    size_t total = (size_t)RR * MMI;
    for (size_t i = (size_t)blockIdx.x*blockDim.x + threadIdx.x; i < total;
         i += (size_t)gridDim.x*blockDim.x) {
        int m = (int)(i % MMI);
        int tb = (int)(i / MMI);
        int b = tb & (BB-1);
        int t = tb >> 6;
        g_di[i] = (t == 0) ? 0.0f : dec[((size_t)b*TMEL + (2*t-1))*MMI + m];
    }
}

__global__ void add_kernel(const float* __restrict__ a, const float* __restrict__ b,
                           float* __restrict__ c, size_t n)
{
    for (size_t i = (size_t)blockIdx.x*blockDim.x + threadIdx.x; i < n;
         i += (size_t)gridDim.x*blockDim.x)
        c[i] = a[i] + b[i];
}

// ---------------- generic fused GEMM:  C = concat(A1,A2) @ W^T + bias ----------------
// A1:[RR,K1], A2:[RR,K2] (optional), W:[N,K1+K2] row-major, tile 128x128x8, 8x8/thread.
__global__ __launch_bounds__(256)
void gemm128(const float* __restrict__ A1, int K1,
             const float* __restrict__ A2, int K2,
             const float* __restrict__ W,  const float* __restrict__ bias,
             float* __restrict__ C, int N, int doRelu, int outBT)
{
    __shared__ float As[8][132];
    __shared__ float Ws[8][132];
    const int K = K1 + K2;
    const int tid  = threadIdx.x;
    const int row0 = blockIdx.y * 128;
    const int n0   = blockIdx.x * 128;
    const int ty = tid >> 4, tx = tid & 15;
    const int lm = tid >> 1;          // 0..127
    const int lk = (tid & 1) * 4;     // 0 or 4

    float acc[8][8];
#pragma unroll
    for (int i = 0; i < 8; i++)
#pragma unroll
        for (int j = 0; j < 8; j++) acc[i][j] = 0.0f;

    for (int kc = 0; kc < K; kc += 8) {
        int k = kc + lk;
        float4 av;
        if (k < K1) av = *(const float4*)(A1 + (size_t)(row0+lm)*K1 + k);
        else        av = *(const float4*)(A2 + (size_t)(row0+lm)*K2 + (k - K1));
        float4 wv = make_float4(0.f,0.f,0.f,0.f);
        int nr = n0 + lm;
        if (nr < N) wv = *(const float4*)(W + (size_t)nr*K + k);

        As[lk+0][lm]=av.x; As[lk+1][lm]=av.y; As[lk+2][lm]=av.z; As[lk+3][lm]=av.w;
        Ws[lk+0][lm]=wv.x; Ws[lk+1][lm]=wv.y; Ws[lk+2][lm]=wv.z; Ws[lk+3][lm]=wv.w;
        __syncthreads();
#pragma unroll
        for (int kk = 0; kk < 8; kk++) {
            float a[8], w[8];
#pragma unroll
            for (int i = 0; i < 8; i++) a[i] = As[kk][ty*8+i];
#pragma unroll
            for (int j = 0; j < 8; j++) w[j] = Ws[kk][tx*8+j];
#pragma unroll
            for (int i = 0; i < 8; i++)
#pragma unroll
                for (int j = 0; j < 8; j++)
                    acc[i][j] = fmaf(a[i], w[j], acc[i][j]);
        }
        __syncthreads();
    }

#pragma unroll
    for (int i = 0; i < 8; i++) {
        int m = row0 + ty*8 + i;
#pragma unroll
        for (int j = 0; j < 8; j++) {
            int n = n0 + tx*8 + j;
            if (n < N) {
                float v = acc[i][j] + bias[n];
                if (doRelu) v = fmaxf(v, 0.0f);
                if (outBT) {
                    int t = m >> 6, b = m & (BB-1);
                    C[((size_t)b*TD + t)*N + n] = v;
                } else {
                    C[(size_t)m*N + n] = v;
                }
            }
        }
    }
}

// ---------------- persistent GRU recurrence pass ----------------
// One launch per GRU pass. 128 CTAs (co-resident on 148 SMs) loop over all
// timesteps with a software grid barrier between steps.
// Per step: gh = h_prev @ whh^T + bhh, then fused GRU nonlinearity with
// precomputed input gates gi.
__device__ __forceinline__ float sigmoidf(float x) { return 1.0f/(1.0f + expf(-x)); }

#define GRU_NBLK 128

__device__ __forceinline__ void grid_barrier()
{
    __syncthreads();
    if (threadIdx.x == 0) {
        __threadfence();
        unsigned g = *(volatile unsigned*)&g_bargen;
        unsigned old = atomicAdd(&g_barcnt, 1u);
        if (old == GRU_NBLK - 1u) {
            atomicExch(&g_barcnt, 0u);
            __threadfence();
            atomicAdd(&g_bargen, 1u);
        } else {
            while (*(volatile unsigned*)&g_bargen == g) { }
        }
        __threadfence();
    }
    __syncthreads();
}

__global__ __launch_bounds__(384, 1)
void gru_pass(int pass, const float* __restrict__ whh, const float* __restrict__ bhh)
{
    float* hall = (pass == 0) ? g_h1 : (pass == 1) ? g_h2 : g_h3;

    extern __shared__ float sm[];
    float* hs  = sm;              // [128][68]  staged h chunk  (34816 B)
    float* ws  = sm + 128*68;     // [128][24]  staged w chunk  (12288 B)
    float* red = sm;              // [8][24][64] reduction      (49152 B, aliased)

    const int tid = threadIdx.x;               // 384
    const int j0  = blockIdx.x * 8;
    const int bg  = tid & 7;                   // 8 groups of 8 batch rows
    const int rg  = (tid >> 3) % 6;            // 6 groups of 4 gate rows
    const int ks  = tid / 48;                  // 8-way K split

    for (int t = 0; t < TD; t++) {
        const float* gi    = g_gi + (size_t)t * BB * 3 * HH;
        const float* hprev = hall + (size_t)(t-1) * BB * HH;   // unused when t==0
        float*       hout  = hall + (size_t)t * BB * HH;

        float acc[4][8];
#pragma unroll
        for (int r = 0; r < 4; r++)
#pragma unroll
            for (int i = 0; i < 8; i++) acc[r][i] = 0.0f;

        if (t > 0) {
            for (int kc = 0; kc < HH; kc += 128) {
                __syncthreads();
                // stage h chunk transposed: hs[k][b]
                for (int e = tid; e < 64*128; e += 384) {
                    int b = e >> 7, kk = e & 127;
                    hs[kk*68 + b] = hprev[(size_t)b*HH + kc + kk];
                }
                // stage 24 weight rows transposed: ws[k][lr]
                for (int e = tid; e < 24*128; e += 384) {
                    int lr = e >> 7, kk = e & 127;
                    int g = lr >> 3, jj = lr & 7;
                    ws[kk*24 + lr] = whh[(size_t)(g*HH + j0 + jj)*HH + kc + kk];
                }
                __syncthreads();
                const int kbase = ks * 16;
#pragma unroll
                for (int ki = 0; ki < 16; ki++) {
                    const float* hp = hs + (kbase + ki)*68 + bg*8;
                    const float* wp = ws + (kbase + ki)*24 + rg*4;
                    float hv[8], wv[4];
#pragma unroll
                    for (int i = 0; i < 8; i++) hv[i] = hp[i];
#pragma unroll
                    for (int r = 0; r < 4; r++) wv[r] = wp[r];
#pragma unroll
                    for (int r = 0; r < 4; r++)
#pragma unroll
                        for (int i = 0; i < 8; i++)
                            acc[r][i] = fmaf(wv[r], hv[i], acc[r][i]);
                }
            }
        }
        __syncthreads();
        // write K-split partials: red[ks][lr][b]
#pragma unroll
        for (int r = 0; r < 4; r++)
#pragma unroll
            for (int i = 0; i < 8; i++)
                red[((size_t)ks*24 + rg*4 + r)*64 + bg*8 + i] = acc[r][i];
        __syncthreads();
        // reduce 8 slices + bhh -> red[0][lr][b]
        for (int o = tid; o < 24*64; o += 384) {
            int lr = o >> 6, b = o & 63;
            float s = bhh[(lr >> 3)*HH + j0 + (lr & 7)];
#pragma unroll
            for (int q = 0; q < 8; q++) s += red[((size_t)q*24 + lr)*64 + b];
            red[(size_t)lr*64 + b] = s;
        }
        __syncthreads();
        // fused GRU update (gate order r, z, n)
        for (int o = tid; o < 8*64; o += 384) {
            int jj = o >> 6, b = o & 63;
            int j = j0 + jj;
            float gr = red[(size_t)(jj     )*64 + b];
            float gz = red[(size_t)(8  + jj)*64 + b];
            float gn = red[(size_t)(16 + jj)*64 + b];
            const float* gib = gi + (size_t)b*3*HH;
            float r  = sigmoidf(gib[j]        + gr);
            float z  = sigmoidf(gib[HH  + j]  + gz);
            float n  = tanhf   (gib[2*HH + j] + r*gn);
            float hp = (t > 0) ? hprev[(size_t)b*HH + j] : 0.0f;
            hout[(size_t)b*HH + j] = (1.0f - z)*n + z*hp;
        }
        // all CTAs must finish step t before any reads hout as hprev at t+1
        grid_barrier();
    }
}

// ---------------- host orchestration ----------------
extern "C" void kernel_launch(void* const* d_in, const int* in_sizes, int n_in,
                              void* d_out, int out_size)
{
    const float* memorys = (const float*)d_in[0];
    const float* dec     = (const float*)d_in[1];
    // d_in[2] memory_lengths: unused by reference decode path
    const float* pre_w1 = (const float*)d_in[3];
    const float* pre_b1 = (const float*)d_in[4];
    const float* pre_w2 = (const float*)d_in[5];
    const float* pre_b2 = (const float*)d_in[6];
    const float* g1_wih = (const float*)d_in[7];
    const float* g1_whh = (const float*)d_in[8];
    const float* g1_bih = (const float*)d_in[9];
    const float* g1_bhh = (const float*)d_in[10];
    const float* att_w  = (const float*)d_in[11];
    const float* att_b  = (const float*)d_in[12];
    const float* g2_wih = (const float*)d_in[13];
    const float* g2_whh = (const float*)d_in[14];
    const float* g2_bih = (const float*)d_in[15];
    const float* g2_bhh = (const float*)d_in[16];
    const float* g3_wih = (const float*)d_in[17];
    const float* g3_whh = (const float*)d_in[18];
    const float* g3_bih = (const float*)d_in[19];
    const float* g3_bhh = (const float*)d_in[20];
    const float* proj_w = (const float*)d_in[21];
    const float* proj_b = (const float*)d_in[22];
    float* out = (float*)d_out;

    float *p_di,*p_mem,*p_xa,*p_xb,*p_gi,*p_h1,*p_h2,*p_h3,*p_d2,*p_r2;
    cudaGetSymbolAddress((void**)&p_di,  g_di);
    cudaGetSymbolAddress((void**)&p_mem, g_mem);
    cudaGetSymbolAddress((void**)&p_xa,  g_xa);
    cudaGetSymbolAddress((void**)&p_xb,  g_xb);
    cudaGetSymbolAddress((void**)&p_gi,  g_gi);
    cudaGetSymbolAddress((void**)&p_h1,  g_h1);
    cudaGetSymbolAddress((void**)&p_h2,  g_h2);
    cudaGetSymbolAddress((void**)&p_h3,  g_h3);
    cudaGetSymbolAddress((void**)&p_d2,  g_d2);
    cudaGetSymbolAddress((void**)&p_r2,  g_r2);

    cudaFuncSetAttribute(gru_pass, cudaFuncAttributeMaxDynamicSharedMemorySize, 64*1024);
    const int GRU_SMEM = 8*24*64*4;   // 49152 B (>= staging 47104 B)

    // prep
    pool_kernel<<<4096, 256>>>(memorys);
    di_kernel  <<<4096, 256>>>(dec);

    auto gemm = [&](const float* A1, int K1, const float* A2, int K2,
                    const float* W, const float* b, float* C, int N,
                    int relu, int bt) {
        dim3 grid((N + 127)/128, RR/128);
        gemm128<<<grid, 256>>>(A1, K1, A2, K2, W, b, C, N, relu, bt);
    };

    // prenet
    gemm(p_di, MMI, nullptr, 0, pre_w1, pre_b1, p_xa, PP, 1, 0);
    gemm(p_xa, PP,  nullptr, 0, pre_w2, pre_b2, p_xb, PP, 1, 0);

    // GRU1 input gates (batched over all timesteps) + recurrence
    gemm(p_xb, PP, p_mem, EE, g1_wih, g1_bih, p_gi, 3*HH, 0, 0);
    gru_pass<<<GRU_NBLK, 384, GRU_SMEM>>>(0, g1_whh, g1_bhh);

    // attention linear + GRU2 input gates (batched) + recurrence
    gemm(p_h1, HH, p_mem, EE, att_w, att_b, p_d2, HH, 0, 0);
    gemm(p_d2, HH, nullptr, 0, g2_wih, g2_bih, p_gi, 3*HH, 0, 0);
    gru_pass<<<GRU_NBLK, 384, GRU_SMEM>>>(1, g2_whh, g2_bhh);

    // r2 = h2 + d2
    add_kernel<<<8192, 256>>>(p_h2, p_d2, p_r2, (size_t)RR*HH);

    // GRU3 input gates (batched) + recurrence
    gemm(p_r2, HH, nullptr, 0, g3_wih, g3_bih, p_gi, 3*HH, 0, 0);
    gru_pass<<<GRU_NBLK, 384, GRU_SMEM>>>(2, g3_whh, g3_bhh);

    // r3 = h3 + r2 (into g_d2)
    add_kernel<<<8192, 256>>>(p_h3, p_r2, p_d2, (size_t)RR*HH);

    // projection, writing directly in [B,T,160] layout
    gemm(p_d2, HH, p_mem, EE, proj_w, proj_b, out, MMI*2, 0, 1);
}